// round 17
// baseline (speedup 1.0000x reference)
#include <cuda_runtime.h>
#include <cstdint>

// Problem shape (fixed for this dataset entry)
#define BB 8
#define CC 81
#define HH 96
#define WW 320
#define NN 16
#define HWSZ (HH * WW)            // 30720
#define TPB 256
#define BATCH 9                   // 81 = 9*9
#define NBLK (BB * HWSZ / TPB)    // 960 blocks, 1 px/thread

#define ALPHA_F   0.25f
#define FG_W_F    13.0f
#define BG_W_F    1.0f
#define DEPTH_MIN_F 0.001f
#define DEPTH_MAX_F 60.0f
#define NUM_BINS_I  80

// Cross-block accumulator (zero at load; last block resets -> deterministic per replay)
__device__ float    g_scratch = 0.0f;
__device__ unsigned g_count   = 0u;

__global__ __launch_bounds__(TPB, 5) void ddn_loss_kernel(
    const float* __restrict__ logits,   // (B,C,H,W)
    const float* __restrict__ boxes,    // (B*N,4)
    const float* __restrict__ depths,   // (B*N,)
    float* __restrict__ out)            // scalar
{
    __shared__ int   sbu1[NN], sbv1[NN], sbu2[NN], sbv2[NN];
    __shared__ float sdep[NN];
    __shared__ float sred[8];

    const int t   = threadIdx.x;
    const int g   = blockIdx.x * TPB + t;        // one pixel per thread
    const int b   = g / HWSZ;                    // block never crosses batch (30720 % 256 == 0)
    const int rem = g - b * HWSZ;
    const int h   = rem / WW;
    const int w   = rem - h * WW;

    // Base of this pixel within batch b's plane stack.
    const float* __restrict__ gsrc = logits + (size_t)b * CC * HWSZ + rem;

    // ---- Prologue: TWO batches (18 loads) in flight before any ALU ----
    float bA[BATCH], bB[BATCH], bC[BATCH];
#pragma unroll
    for (int i = 0; i < BATCH; i++)
        bA[i] = gsrc[(size_t)i * HWSZ];                      // batch 0
#pragma unroll
    for (int i = 0; i < BATCH; i++)
        bB[i] = gsrc[(size_t)(BATCH + i) * HWSZ];            // batch 1

    if (t < NN) {
        const int i = b * NN + t;
        sbu1[t] = (int)floorf(boxes[4 * i + 0]);
        sbv1[t] = (int)floorf(boxes[4 * i + 1]);
        sbu2[t] = (int)ceilf (boxes[4 * i + 2]);
        sbv2[t] = (int)ceilf (boxes[4 * i + 3]);
        sdep[t] = depths[i];
    }
    __syncthreads();

    // ---- Rasterize + LID binning (overlaps with the in-flight loads) ----
    float dmin = 1e10f;
    bool  fg   = false;
#pragma unroll
    for (int i = 0; i < NN; i++) {
        const bool cov = (h >= sbv1[i]) & (h < sbv2[i]) &
                         (w >= sbu1[i]) & (w < sbu2[i]);
        if (cov) { fg = true; dmin = fminf(dmin, sdep[i]); }
    }
    const float d   = fg ? dmin : 0.0f;
    const float wgt = fg ? FG_W_F : BG_W_F;
    const float bin_size = 2.0f * (DEPTH_MAX_F - DEPTH_MIN_F)
                           / ((float)NUM_BINS_I * (1.0f + (float)NUM_BINS_I));
    float idxf = -0.5f + 0.5f * sqrtf(1.0f + 8.0f * (d - DEPTH_MIN_F) / bin_size);
    if (!(idxf >= 0.0f) || idxf > (float)NUM_BINS_I) idxf = (float)NUM_BINS_I;
    const int tgt = (int)idxf;                    // truncation toward zero

    // Target logit (line also touched by the stream)
    const float xt = gsrc[(size_t)tgt * HWSZ];

    // ---- Stream 81 channels: modulo-3 rolling buffers, 2 batches always in
    //      flight, ZERO rotation copies (buffer names static via x3 unroll) ----
    float s = 0.f;
#pragma unroll 1
    for (int rr = 0; rr < 2; rr++) {             // rounds 0..5 (two periods of 3)
        const float* p0 = gsrc + (size_t)(rr * 3 + 2) * BATCH * HWSZ;
#pragma unroll
        for (int i = 0; i < BATCH; i++) bC[i] = p0[(size_t)i * HWSZ];
#pragma unroll
        for (int i = 0; i < BATCH; i++) s += __expf(bA[i]);

        const float* p1 = gsrc + (size_t)(rr * 3 + 3) * BATCH * HWSZ;
#pragma unroll
        for (int i = 0; i < BATCH; i++) bA[i] = p1[(size_t)i * HWSZ];
#pragma unroll
        for (int i = 0; i < BATCH; i++) s += __expf(bB[i]);

        const float* p2 = gsrc + (size_t)(rr * 3 + 4) * BATCH * HWSZ;
#pragma unroll
        for (int i = 0; i < BATCH; i++) bB[i] = p2[(size_t)i * HWSZ];
#pragma unroll
        for (int i = 0; i < BATCH; i++) s += __expf(bC[i]);
    }
    // Round 6: load batch 8, consume batch 6 (in bA)
    {
        const float* p = gsrc + (size_t)8 * BATCH * HWSZ;
#pragma unroll
        for (int i = 0; i < BATCH; i++) bC[i] = p[(size_t)i * HWSZ];
#pragma unroll
        for (int i = 0; i < BATCH; i++) s += __expf(bA[i]);
    }
    // Drain batch 7 (bB) and batch 8 (bC)
#pragma unroll
    for (int i = 0; i < BATCH; i++) s += __expf(bB[i]);
#pragma unroll
    for (int i = 0; i < BATCH; i++) s += __expf(bC[i]);

    // ---- Focal loss, weighted ----
    const float lp = xt - __logf(s);
    const float pt = __expf(lp);
    float local = wgt * (-ALPHA_F * (1.f - pt) * (1.f - pt) * lp);

    // ---- Block reduction ----
#pragma unroll
    for (int o = 16; o > 0; o >>= 1)
        local += __shfl_xor_sync(0xffffffffu, local, o);
    if ((t & 31) == 0) sred[t >> 5] = local;
    __syncthreads();

    // ---- Grid reduction fused into the kernel ----
    if (t == 0) {
        float v = 0.f;
#pragma unroll
        for (int i = 0; i < 8; i++) v += sred[i];
        atomicAdd(&g_scratch, v);
        __threadfence();
        const unsigned ticket = atomicAdd(&g_count, 1u);
        if (ticket == (unsigned)(gridDim.x - 1)) {
            // All prior scratch adds are visible (fence before ticket).
            const float tot = atomicAdd(&g_scratch, 0.0f);   // coherent read
            const float inv_np = 1.0f / (float)(BB * HH * WW);
            out[0] = tot * inv_np;
            // Reset for the next graph replay: deterministic invariant.
            g_scratch = 0.0f;
            __threadfence();
            g_count = 0u;
        }
    }
}

extern "C" void kernel_launch(void* const* d_in, const int* in_sizes, int n_in,
                              void* d_out, int out_size) {
    const float* logits = (const float*)d_in[0];   // depth_logits (B,C,H,W) f32
    const float* boxes  = (const float*)d_in[1];   // gt_boxes2d (B*N,4) f32
    // d_in[2] = num_gt_per_img (scalar int, constant 16 for this shape)
    const float* depths = (const float*)d_in[3];   // gt_center_depth (B*N,) f32
    float* out = (float*)d_out;

    ddn_loss_kernel<<<NBLK, TPB>>>(logits, boxes, depths, out);
}